// round 8
// baseline (speedup 1.0000x reference)
#include <cuda_runtime.h>
#include <cuda_fp16.h>
#include <math_constants.h>
#include <cstdint>

constexpr int B = 32, N = 2000, NPAD = 2048, D = 25088;
constexpr int ITOT = D / 64;     // 392 k-iters (dots)
constexpr int KC   = 18;         // dots k-chunks
constexpr int RSTEP = NPAD / 16; // 128 global k-steps for read (16 n each)
constexpr int RIT2  = 16;        // read n-iters per n-chunk (2 chunks)

constexpr float EPS = 1e-8f, PI_2C = 3.14159f * 0.5f;

__device__ float  g_part[KC * B * NPAD];
__device__ float  g_msq [KC * NPAD];
__device__ uint4  g_kb  [ITOT * 4 * 32 * 2];  // key prepacked (dots B frags)
__device__ float  g_kn  [B];
__device__ float  g_sum [B];
__device__ float  g_ev  [B * NPAD];
__device__ __half g_whi [B * NPAD];           // padding [2000,2048) stays 0
__device__ __half g_wlo [B * NPAD];
__device__ uint4  g_wf  [RSTEP * 32 * 4];     // w prepacked (read A frags)
__device__ float  g_rout[2 * B * D];          // read n-chunk partials

__device__ __forceinline__ uint32_t smem_u32(const void* p) {
    uint32_t a;
    asm("{ .reg .u64 t; cvta.to.shared.u64 t, %1; cvt.u32.u64 %0, t; }" : "=r"(a) : "l"(p));
    return a;
}
__device__ __forceinline__ void ldm4t(uint32_t& r0, uint32_t& r1, uint32_t& r2, uint32_t& r3, uint32_t a) {
    asm volatile("ldmatrix.sync.aligned.m8n8.x4.trans.shared.b16 {%0,%1,%2,%3}, [%4];"
                 : "=r"(r0), "=r"(r1), "=r"(r2), "=r"(r3) : "r"(a));
}
__device__ __forceinline__ void mma_h(float* c, uint32_t a0, uint32_t a1, uint32_t a2, uint32_t a3,
                                      uint32_t b0, uint32_t b1) {
    asm volatile("mma.sync.aligned.m16n8k16.row.col.f32.f16.f16.f32 "
                 "{%0,%1,%2,%3}, {%4,%5,%6,%7}, {%8,%9}, {%0,%1,%2,%3};"
                 : "+f"(c[0]), "+f"(c[1]), "+f"(c[2]), "+f"(c[3])
                 : "r"(a0), "r"(a1), "r"(a2), "r"(a3), "r"(b0), "r"(b1));
}
__device__ __forceinline__ uint32_t h2(float a, float b) {
    __half2 h = __floats2half2_rn(a, b);
    return *(uint32_t*)&h;
}

// ---------------------------------------------------------------------------
// Kernel 0: prepack key -> dots B fragments. Grid 196 x 256. (unchanged, proven)
// ---------------------------------------------------------------------------
__global__ __launch_bounds__(256) void prepack_kernel(const float* __restrict__ key)
{
    const int gid = blockIdx.x * 256 + threadIdx.x;
    const int t = gid & 31, s = gid >> 5;
    const int d = (s >> 2) * 64 + (s & 3) * 16 + 2 * (t & 3);
    uint32_t v0[4], v1[4];
    #pragma unroll
    for (int nf = 0; nf < 4; nf++) {
        const int row = (t >> 2) + 8 * nf;
        const float2 x0 = *(const float2*)&key[row * D + d];
        const float2 x1 = *(const float2*)&key[row * D + d + 8];
        v0[nf] = h2(x0.x, x0.y);
        v1[nf] = h2(x1.x, x1.y);
    }
    g_kb[(s * 32 + t) * 2    ] = make_uint4(v0[0], v0[1], v0[2], v0[3]);
    g_kb[(s * 32 + t) * 2 + 1] = make_uint4(v1[0], v1[1], v1[2], v1[3]);
}

// ---------------------------------------------------------------------------
// Kernel 1: dots^T partials + m-norm partials. (unchanged from R7, proven)
// ---------------------------------------------------------------------------
__global__ __launch_bounds__(256) void dots_kernel(const float* __restrict__ mem)
{
    const int tid = threadIdx.x, w = tid >> 5, t = tid & 31;
    const int n0 = blockIdx.x * 128, kc = blockIdx.y;
    const int it0 = kc * ITOT / KC, it1 = (kc + 1) * ITOT / KC;
    const int nst = (it1 - it0) * 4;
    const int r0 = n0 + w * 16 + (t >> 2);
    const int qc = 2 * (t & 3);
    const bool ok0 = r0 < N, ok1 = (r0 + 8) < N;
    const float* q0 = mem + (long long)(ok0 ? r0 : 0) * D + it0 * 64 + qc;
    const float* q1 = mem + (long long)(ok1 ? r0 + 8 : 0) * D + it0 * 64 + qc;
    const uint4* kb = g_kb + ((long long)(it0 * 4) * 32 + t) * 2;

    float acc[4][4];
    #pragma unroll
    for (int f = 0; f < 4; f++)
        #pragma unroll
        for (int i = 0; i < 4; i++) acc[f][i] = 0.f;
    float ms0 = 0.f, ms1 = 0.f;

    float2 fa[2][4]; uint4 fb[2][2];
    fa[0][0] = *(const float2*)q0;
    fa[0][1] = *(const float2*)q1;
    fa[0][2] = *(const float2*)(q0 + 8);
    fa[0][3] = *(const float2*)(q1 + 8);
    fb[0][0] = kb[0];
    fb[0][1] = kb[1];

    for (int j = 0; j < nst; ++j) {
        const int b = j & 1;
        if (j + 1 < nst) {
            const float* a0 = q0 + (j + 1) * 16;
            const float* a1 = q1 + (j + 1) * 16;
            fa[b ^ 1][0] = *(const float2*)a0;
            fa[b ^ 1][1] = *(const float2*)a1;
            fa[b ^ 1][2] = *(const float2*)(a0 + 8);
            fa[b ^ 1][3] = *(const float2*)(a1 + 8);
            fb[b ^ 1][0] = kb[(j + 1) * 64];
            fb[b ^ 1][1] = kb[(j + 1) * 64 + 1];
        }
        float2 f0 = fa[b][0], f1 = fa[b][1], f2v = fa[b][2], f3 = fa[b][3];
        if (!ok0) { f0 = make_float2(0.f, 0.f); f2v = make_float2(0.f, 0.f); }
        if (!ok1) { f1 = make_float2(0.f, 0.f); f3 = make_float2(0.f, 0.f); }
        ms0 = fmaf(f0.x, f0.x, fmaf(f0.y, f0.y, ms0));
        ms0 = fmaf(f2v.x, f2v.x, fmaf(f2v.y, f2v.y, ms0));
        ms1 = fmaf(f1.x, f1.x, fmaf(f1.y, f1.y, ms1));
        ms1 = fmaf(f3.x, f3.x, fmaf(f3.y, f3.y, ms1));
        const uint32_t a0 = h2(f0.x, f0.y), a1 = h2(f1.x, f1.y);
        const uint32_t a2 = h2(f2v.x, f2v.y), a3 = h2(f3.x, f3.y);
        const uint4 B0 = fb[b][0], B1 = fb[b][1];
        mma_h(acc[0], a0, a1, a2, a3, B0.x, B1.x);
        mma_h(acc[1], a0, a1, a2, a3, B0.y, B1.y);
        mma_h(acc[2], a0, a1, a2, a3, B0.z, B1.z);
        mma_h(acc[3], a0, a1, a2, a3, B0.w, B1.w);
    }

    const int nrow = n0 + w * 16 + (t >> 2);
    #pragma unroll
    for (int nf = 0; nf < 4; nf++) {
        g_part[(kc * B + 8 * nf + qc    ) * NPAD + nrow    ] = acc[nf][0];
        g_part[(kc * B + 8 * nf + qc + 1) * NPAD + nrow    ] = acc[nf][1];
        g_part[(kc * B + 8 * nf + qc    ) * NPAD + nrow + 8] = acc[nf][2];
        g_part[(kc * B + 8 * nf + qc + 1) * NPAD + nrow + 8] = acc[nf][3];
    }
    ms0 += __shfl_xor_sync(0xffffffffu, ms0, 1);
    ms0 += __shfl_xor_sync(0xffffffffu, ms0, 2);
    ms1 += __shfl_xor_sync(0xffffffffu, ms1, 1);
    ms1 += __shfl_xor_sync(0xffffffffu, ms1, 2);
    if ((t & 3) == 0) {
        g_msq[kc * NPAD + n0 + w * 16 + (t >> 2)    ] = ms0;
        g_msq[kc * NPAD + n0 + w * 16 + (t >> 2) + 8] = ms1;
    }
}

// ---------------------------------------------------------------------------
// Kernel 2a: key norms + reset g_sum (replay-safe). Grid 32 x 256.
// ---------------------------------------------------------------------------
__global__ __launch_bounds__(256) void keynorm_kernel(const float* __restrict__ key)
{
    const int b = blockIdx.x, tid = threadIdx.x;
    __shared__ float red[256];
    float s = 0.f;
    for (int i = tid; i < D; i += 256) { const float v = key[b * D + i]; s = fmaf(v, v, s); }
    red[tid] = s; __syncthreads();
    for (int o = 128; o > 0; o >>= 1) { if (tid < o) red[tid] += red[tid + o]; __syncthreads(); }
    if (tid == 0) {
        g_kn[b]  = fmaxf(sqrtf(red[0]), EPS);
        g_sum[b] = 0.f;
    }
}

// ---------------------------------------------------------------------------
// Kernel 2b: reduce partials + cos -> tan -> exp (shift-free; args are tiny for
// this data), local sum -> atomicAdd. Grid (8 chunks, 32 b) x 256.
// ---------------------------------------------------------------------------
__global__ __launch_bounds__(256) void expsum_kernel()
{
    const int b = blockIdx.y, n = blockIdx.x * 256 + threadIdx.x, tid = threadIdx.x;
    __shared__ float red[256];
    float ev = 0.f;
    if (n < N) {
        float dot = 0.f, ms = 0.f;
        #pragma unroll
        for (int c = 0; c < KC; c++) {
            dot += g_part[(c * B + b) * NPAD + n];
            ms  += g_msq[c * NPAD + n];
        }
        const float mn = fmaxf(sqrtf(ms), EPS);
        ev = expf(tanf((dot / (g_kn[b] * mn)) * PI_2C));
        g_ev[b * NPAD + n] = ev;
    }
    red[tid] = ev; __syncthreads();
    for (int o = 128; o > 0; o >>= 1) { if (tid < o) red[tid] += red[tid + o]; __syncthreads(); }
    if (tid == 0) atomicAdd(&g_sum[b], red[0]);
}

// ---------------------------------------------------------------------------
// Kernel 2c: normalize + split w into fp16 hi/lo. Grid (8, 32) x 256.
// ---------------------------------------------------------------------------
__global__ __launch_bounds__(256) void wsplit_kernel()
{
    const int b = blockIdx.y, n = blockIdx.x * 256 + threadIdx.x;
    if (n < N) {
        const float wv = g_ev[b * NPAD + n] / g_sum[b];
        const __half hi = __float2half(wv);
        g_whi[b * NPAD + n] = hi;
        g_wlo[b * NPAD + n] = __float2half(wv - __half2float(hi));
    }
}

// ---------------------------------------------------------------------------
// Kernel 2d: prepack w -> read A fragments. Grid 16 x 256.
// Step s (16 n), lane t: n_base = s*16 + 2(t&3); rows r = t>>2 (+8/+16/+24).
// 4 uint4: [mf0 hi][mf1 hi][mf0 lo][mf1 lo], each = {a0,a1,a2,a3}.
// ---------------------------------------------------------------------------
__global__ __launch_bounds__(256) void wprepack_kernel()
{
    const int gid = blockIdx.x * 256 + threadIdx.x;   // 0..4095
    const int t = gid & 31, s = gid >> 5;
    const int nb = s * 16 + 2 * (t & 3);
    const int r0 = t >> 2;
    uint4 o[4];
    #pragma unroll
    for (int mf = 0; mf < 2; mf++) {
        const int r = r0 + 16 * mf;
        o[mf] = make_uint4(
            *(const uint32_t*)&g_whi[ r      * NPAD + nb    ],
            *(const uint32_t*)&g_whi[(r + 8) * NPAD + nb    ],
            *(const uint32_t*)&g_whi[ r      * NPAD + nb + 8],
            *(const uint32_t*)&g_whi[(r + 8) * NPAD + nb + 8]);
        o[2 + mf] = make_uint4(
            *(const uint32_t*)&g_wlo[ r      * NPAD + nb    ],
            *(const uint32_t*)&g_wlo[(r + 8) * NPAD + nb    ],
            *(const uint32_t*)&g_wlo[ r      * NPAD + nb + 8],
            *(const uint32_t*)&g_wlo[(r + 8) * NPAD + nb + 8]);
    }
    #pragma unroll
    for (int q = 0; q < 4; q++) g_wf[(s * 32 + t) * 4 + q] = o[q];
}

// ---------------------------------------------------------------------------
// Kernel 3: read partials. Grid (196 d-blocks, 2 n-chunks) x 256 (8 warps).
// B = m tile [64 n][128 d] fp16 in smem (double buf, ldmatrix.trans);
// A = prepacked w fragments (warp-uniform LDG.128, no smem). Warp nj = 16 d.
// hi and lo products accumulate into the SAME accumulator -> no epilogue reduce.
// smem: 2 x 64 x 136 halves = 34816 B.
// ---------------------------------------------------------------------------
__global__ __launch_bounds__(256) void read_kernel(const float* __restrict__ mem)
{
    extern __shared__ __align__(16) __half Bt[];   // [buf][64][136]
    const uint32_t sbB = smem_u32(Bt);
    const int tid = threadIdx.x, w = tid >> 5, t = tid & 31;
    const int d0 = blockIdx.x * 128, nc = blockIdx.y;
    const int nbase = nc * 1024;

    float acc[2][2][4];
    #pragma unroll
    for (int mf = 0; mf < 2; mf++)
        #pragma unroll
        for (int bf = 0; bf < 2; bf++)
            #pragma unroll
            for (int i = 0; i < 4; i++) acc[mf][bf][i] = 0.f;

    float4 rB[8];
    #pragma unroll
    for (int p = 0; p < 8; p++) {
        const int idx = tid + 256 * p, row = idx >> 5, c4 = idx & 31;
        const int n = nbase + row;
        rB[p] = (n < N) ? *(const float4*)&mem[(long long)n * D + d0 + c4 * 4]
                        : make_float4(0.f, 0.f, 0.f, 0.f);
    }

    for (int it = 0; it < RIT2; ++it) {
        const int buf = it & 1;
        __half* Bm = Bt + buf * 64 * 136;
        #pragma unroll
        for (int p = 0; p < 8; p++) {
            const int idx = tid + 256 * p, row = idx >> 5, c4 = idx & 31;
            *(uint2*)&Bm[row * 136 + c4 * 4] = make_uint2(h2(rB[p].x, rB[p].y), h2(rB[p].z, rB[p].w));
        }
        __syncthreads();
        if (it + 1 < RIT2) {
            const int nb = nbase + (it + 1) * 64;
            #pragma unroll
            for (int p = 0; p < 8; p++) {
                const int idx = tid + 256 * p, row = idx >> 5, c4 = idx & 31;
                const int n = nb + row;
                rB[p] = (n < N) ? *(const float4*)&mem[(long long)n * D + d0 + c4 * 4]
                                : make_float4(0.f, 0.f, 0.f, 0.f);
            }
        }
        const int lr = (t & 7) + 8 * ((t >> 3) & 1);
        const int lh = 8 * (t >> 4);
        const int s0 = (nc * RIT2 + it) * 4;          // global k-step base
        #pragma unroll
        for (int kk = 0; kk < 4; kk++) {
            const uint4* wf = &g_wf[((s0 + kk) * 32 + t) * 4];
            uint32_t bq[4];
            ldm4t(bq[0], bq[1], bq[2], bq[3],
                  sbB + 2u * (buf * 64 * 136 + (kk * 16 + lr) * 136 + w * 16 + lh));
            const uint4 A0h = wf[0], A1h = wf[1], A0l = wf[2], A1l = wf[3];
            mma_h(acc[0][0], A0h.x, A0h.y, A0h.z, A0h.w, bq[0], bq[1]);
            mma_h(acc[0][1], A0h.x, A0h.y, A0h.z, A0h.w, bq[2], bq[3]);
            mma_h(acc[1][0], A1h.x, A1h.y, A1h.z, A1h.w, bq[0], bq[1]);
            mma_h(acc[1][1], A1h.x, A1h.y, A1h.z, A1h.w, bq[2], bq[3]);
            mma_h(acc[0][0], A0l.x, A0l.y, A0l.z, A0l.w, bq[0], bq[1]);
            mma_h(acc[0][1], A0l.x, A0l.y, A0l.z, A0l.w, bq[2], bq[3]);
            mma_h(acc[1][0], A1l.x, A1l.y, A1l.z, A1l.w, bq[0], bq[1]);
            mma_h(acc[1][1], A1l.x, A1l.y, A1l.z, A1l.w, bq[2], bq[3]);
        }
        __syncthreads();
    }

    // epilogue: warp owns b rows {t/4, t/4+8} (+16 for mf1) x 16 d cols
    float* ro = g_rout + (long long)nc * B * D;
    #pragma unroll
    for (int mf = 0; mf < 2; mf++)
        #pragma unroll
        for (int bf = 0; bf < 2; bf++) {
            const int b   = mf * 16 + (t >> 2);
            const int col = d0 + w * 16 + bf * 8 + 2 * (t & 3);
            *(float2*)&ro[b * D + col]       = make_float2(acc[mf][bf][0], acc[mf][bf][1]);
            *(float2*)&ro[(b + 8) * D + col] = make_float2(acc[mf][bf][2], acc[mf][bf][3]);
        }
}

// ---------------------------------------------------------------------------
// Kernel 4: out = g_rout[0] + g_rout[1]. Grid 784 x 256, float4.
// ---------------------------------------------------------------------------
__global__ __launch_bounds__(256) void addout_kernel(float* __restrict__ out)
{
    const int i = blockIdx.x * 256 + threadIdx.x;
    const float4 a = ((const float4*)g_rout)[i];
    const float4 b = ((const float4*)g_rout)[i + B * D / 4];
    ((float4*)out)[i] = make_float4(a.x + b.x, a.y + b.y, a.z + b.z, a.w + b.w);
}

// ---------------------------------------------------------------------------
extern "C" void kernel_launch(void* const* d_in, const int* in_sizes, int n_in,
                              void* d_out, int out_size)
{
    const float* key = (const float*)d_in[0];
    const float* mem = (const float*)d_in[1];
    float* out = (float*)d_out;

    cudaFuncSetAttribute(read_kernel, cudaFuncAttributeMaxDynamicSharedMemorySize, 34816);

    prepack_kernel<<<ITOT * 4 * 32 / 256, 256>>>(key);
    dots_kernel<<<dim3(16, KC), 256>>>(mem);
    keynorm_kernel<<<32, 256>>>(key);
    expsum_kernel<<<dim3(8, 32), 256>>>();
    wsplit_kernel<<<dim3(8, 32), 256>>>();
    wprepack_kernel<<<16, 256>>>();
    read_kernel<<<dim3(196, 2), 256, 34816>>>(mem);
    addout_kernel<<<B * D / 4 / 256, 256>>>(out);
}

// round 9
// speedup vs baseline: 1.2314x; 1.2314x over previous
#include <cuda_runtime.h>
#include <cuda_fp16.h>
#include <math_constants.h>
#include <cstdint>
#include <cstring>

constexpr int B = 32, N = 2000, NPAD = 2048, D = 25088;
constexpr int ITOT = D / 64;     // 392 k-iters (dots)
constexpr int KC   = 18;         // dots k-chunks
constexpr int RIT  = NPAD / 64;  // 32 n-iters (read)

constexpr float EPS = 1e-8f, PI_2C = 3.14159f * 0.5f;

__device__ float  g_part[KC * B * NPAD];
__device__ float  g_msq [KC * NPAD];
__device__ uint4  g_kb  [ITOT * 4 * 32 * 2];  // key prepacked in mma-fragment order
__device__ __half g_whi [B * NPAD];           // padding [2000,2048) stays 0
__device__ __half g_wlo [B * NPAD];

// packed f32x2 self-square FMA (compiles on this harness; proven R1/R2)
#define FMA2SQ(d, v) asm("fma.rn.f32x2 %0, %1, %1, %0;" : "+l"(d) : "l"(v))

__device__ __forceinline__ unsigned long long as_u64(float2 v) {
    unsigned long long u; memcpy(&u, &v, 8); return u;
}
__device__ __forceinline__ uint32_t smem_u32(const void* p) {
    uint32_t a;
    asm("{ .reg .u64 t; cvta.to.shared.u64 t, %1; cvt.u32.u64 %0, t; }" : "=r"(a) : "l"(p));
    return a;
}
__device__ __forceinline__ void ldm4(uint32_t& r0, uint32_t& r1, uint32_t& r2, uint32_t& r3, uint32_t a) {
    asm volatile("ldmatrix.sync.aligned.m8n8.x4.shared.b16 {%0,%1,%2,%3}, [%4];"
                 : "=r"(r0), "=r"(r1), "=r"(r2), "=r"(r3) : "r"(a));
}
__device__ __forceinline__ void ldm4t(uint32_t& r0, uint32_t& r1, uint32_t& r2, uint32_t& r3, uint32_t a) {
    asm volatile("ldmatrix.sync.aligned.m8n8.x4.trans.shared.b16 {%0,%1,%2,%3}, [%4];"
                 : "=r"(r0), "=r"(r1), "=r"(r2), "=r"(r3) : "r"(a));
}
__device__ __forceinline__ void mma_h(float* c, uint32_t a0, uint32_t a1, uint32_t a2, uint32_t a3,
                                      uint32_t b0, uint32_t b1) {
    asm volatile("mma.sync.aligned.m16n8k16.row.col.f32.f16.f16.f32 "
                 "{%0,%1,%2,%3}, {%4,%5,%6,%7}, {%8,%9}, {%0,%1,%2,%3};"
                 : "+f"(c[0]), "+f"(c[1]), "+f"(c[2]), "+f"(c[3])
                 : "r"(a0), "r"(a1), "r"(a2), "r"(a3), "r"(b0), "r"(b1));
}
__device__ __forceinline__ uint32_t h2(float a, float b) {
    __half2 h = __floats2half2_rn(a, b);
    return *(uint32_t*)&h;
}

// ---------------------------------------------------------------------------
// Kernel 0: prepack key -> dots B fragments. Grid 196 x 256. (proven)
// ---------------------------------------------------------------------------
__global__ __launch_bounds__(256) void prepack_kernel(const float* __restrict__ key)
{
    const int gid = blockIdx.x * 256 + threadIdx.x;
    const int t = gid & 31, s = gid >> 5;
    const int d = (s >> 2) * 64 + (s & 3) * 16 + 2 * (t & 3);
    uint32_t v0[4], v1[4];
    #pragma unroll
    for (int nf = 0; nf < 4; nf++) {
        const int row = (t >> 2) + 8 * nf;
        const float2 x0 = *(const float2*)&key[row * D + d];
        const float2 x1 = *(const float2*)&key[row * D + d + 8];
        v0[nf] = h2(x0.x, x0.y);
        v1[nf] = h2(x1.x, x1.y);
    }
    g_kb[(s * 32 + t) * 2    ] = make_uint4(v0[0], v0[1], v0[2], v0[3]);
    g_kb[(s * 32 + t) * 2 + 1] = make_uint4(v1[0], v1[1], v1[2], v1[3]);
}

// ---------------------------------------------------------------------------
// Kernel 1: dots^T partials + m-norm partials. No smem, register-pipelined.
// Instruction diet vs R7: no per-step guards (clamped rows produce finite
// garbage only in n>=N outputs, which softmax ignores), norm FMAs packed
// f32x2, running g_kb pointer.
// ---------------------------------------------------------------------------
__global__ __launch_bounds__(256) void dots_kernel(const float* __restrict__ mem)
{
    const int tid = threadIdx.x, w = tid >> 5, t = tid & 31;
    const int n0 = blockIdx.x * 128, kc = blockIdx.y;
    const int it0 = kc * ITOT / KC, it1 = (kc + 1) * ITOT / KC;
    const int nst = (it1 - it0) * 4;
    const int r0 = n0 + w * 16 + (t >> 2);
    const int qc = 2 * (t & 3);
    const int cr0 = r0 < N ? r0 : 0;            // clamped rows
    const int cr1 = (r0 + 8) < N ? (r0 + 8) : 0;
    const float* q0 = mem + (long long)cr0 * D + it0 * 64 + qc;
    const float* q1 = mem + (long long)cr1 * D + it0 * 64 + qc;
    const uint4* kb = g_kb + ((long long)(it0 * 4) * 32 + t) * 2;

    float acc[4][4];
    #pragma unroll
    for (int f = 0; f < 4; f++)
        #pragma unroll
        for (int i = 0; i < 4; i++) acc[f][i] = 0.f;
    unsigned long long msA = 0ull, msB = 0ull;   // packed f32x2 norm accumulators

    float2 fa[2][4]; uint4 fb[2][2];
    fa[0][0] = *(const float2*)q0;
    fa[0][1] = *(const float2*)q1;
    fa[0][2] = *(const float2*)(q0 + 8);
    fa[0][3] = *(const float2*)(q1 + 8);
    fb[0][0] = kb[0];
    fb[0][1] = kb[1];

    for (int j = 0; j < nst; ++j) {
        const int b = j & 1;
        if (j + 1 < nst) {
            const float* a0 = q0 + (j + 1) * 16;
            const float* a1 = q1 + (j + 1) * 16;
            fa[b ^ 1][0] = *(const float2*)a0;
            fa[b ^ 1][1] = *(const float2*)a1;
            fa[b ^ 1][2] = *(const float2*)(a0 + 8);
            fa[b ^ 1][3] = *(const float2*)(a1 + 8);
            kb += 64;
            fb[b ^ 1][0] = kb[0];
            fb[b ^ 1][1] = kb[1];
        }
        const float2 f0 = fa[b][0], f1 = fa[b][1], f2v = fa[b][2], f3 = fa[b][3];
        FMA2SQ(msA, as_u64(f0));
        FMA2SQ(msA, as_u64(f2v));
        FMA2SQ(msB, as_u64(f1));
        FMA2SQ(msB, as_u64(f3));
        const uint32_t a0 = h2(f0.x, f0.y), a1 = h2(f1.x, f1.y);
        const uint32_t a2 = h2(f2v.x, f2v.y), a3 = h2(f3.x, f3.y);
        const uint4 B0 = fb[b][0], B1 = fb[b][1];
        mma_h(acc[0], a0, a1, a2, a3, B0.x, B1.x);
        mma_h(acc[1], a0, a1, a2, a3, B0.y, B1.y);
        mma_h(acc[2], a0, a1, a2, a3, B0.z, B1.z);
        mma_h(acc[3], a0, a1, a2, a3, B0.w, B1.w);
    }

    // C[n_local][b] -> g_part[kc][b][n]  (rows >= N hold garbage; softmax guards)
    const int nrow = n0 + w * 16 + (t >> 2);
    #pragma unroll
    for (int nf = 0; nf < 4; nf++) {
        g_part[(kc * B + 8 * nf + qc    ) * NPAD + nrow    ] = acc[nf][0];
        g_part[(kc * B + 8 * nf + qc + 1) * NPAD + nrow    ] = acc[nf][1];
        g_part[(kc * B + 8 * nf + qc    ) * NPAD + nrow + 8] = acc[nf][2];
        g_part[(kc * B + 8 * nf + qc + 1) * NPAD + nrow + 8] = acc[nf][3];
    }
    float2 mA, mB;
    memcpy(&mA, &msA, 8); memcpy(&mB, &msB, 8);
    float ms0 = mA.x + mA.y, ms1 = mB.x + mB.y;
    ms0 += __shfl_xor_sync(0xffffffffu, ms0, 1);
    ms0 += __shfl_xor_sync(0xffffffffu, ms0, 2);
    ms1 += __shfl_xor_sync(0xffffffffu, ms1, 1);
    ms1 += __shfl_xor_sync(0xffffffffu, ms1, 2);
    if ((t & 3) == 0) {
        g_msq[kc * NPAD + n0 + w * 16 + (t >> 2)    ] = ms0;
        g_msq[kc * NPAD + n0 + w * 16 + (t >> 2) + 8] = ms1;
    }
}

// ---------------------------------------------------------------------------
// Kernel 2: norms + reduce partials + tan + softmax -> w split hi/lo fp16
// (R7 verbatim, proven)
// ---------------------------------------------------------------------------
__global__ __launch_bounds__(256) void softmax_kernel(const float* __restrict__ key)
{
    const int b = blockIdx.x, tid = threadIdx.x;
    __shared__ float red[256];
    float s = 0.f;
    for (int i = tid; i < D; i += 256) { const float v = key[b * D + i]; s = fmaf(v, v, s); }
    red[tid] = s; __syncthreads();
    for (int o = 128; o > 0; o >>= 1) { if (tid < o) red[tid] += red[tid + o]; __syncthreads(); }
    const float knorm = fmaxf(sqrtf(red[0]), EPS);
    __syncthreads();

    float sv[8], lmax = -CUDART_INF_F;
    #pragma unroll
    for (int j = 0; j < 8; j++) {
        const int n = tid + 256 * j;
        if (n < N) {
            float dot = 0.f, ms = 0.f;
            #pragma unroll
            for (int c = 0; c < KC; c++) {
                dot += g_part[(c * B + b) * NPAD + n];
                ms  += g_msq[c * NPAD + n];
            }
            const float mn = fmaxf(sqrtf(ms), EPS);
            sv[j] = tanf((dot / (knorm * mn)) * PI_2C);
            lmax = fmaxf(lmax, sv[j]);
        } else sv[j] = -CUDART_INF_F;
    }
    red[tid] = lmax; __syncthreads();
    for (int o = 128; o > 0; o >>= 1) { if (tid < o) red[tid] = fmaxf(red[tid], red[tid+o]); __syncthreads(); }
    const float mx = red[0];
    __syncthreads();

    float ev[8], ls = 0.f;
    #pragma unroll
    for (int j = 0; j < 8; j++) {
        const int n = tid + 256 * j;
        ev[j] = (n < N) ? expf(sv[j] - mx) : 0.f;
        ls += ev[j];
    }
    red[tid] = ls; __syncthreads();
    for (int o = 128; o > 0; o >>= 1) { if (tid < o) red[tid] += red[tid + o]; __syncthreads(); }
    const float inv = 1.f / red[0];
    #pragma unroll
    for (int j = 0; j < 8; j++) {
        const int n = tid + 256 * j;
        if (n < N) {
            const float wv = ev[j] * inv;
            const __half hi = __float2half(wv);
            g_whi[b * NPAD + n] = hi;
            g_wlo[b * NPAD + n] = __float2half(wv - __half2float(hi));
        }
    }
}

// ---------------------------------------------------------------------------
// Kernel 3: out[b,d] = sum_n w[b,n] m[n,d]. Grid 392 (d-tile 64), 256 thr.
// R7 structure (proven); only change: rB zero-guard -> address clamp
// (garbage rows multiply w=0 padding).
// ---------------------------------------------------------------------------
__global__ __launch_bounds__(256) void read_kernel(
    const float* __restrict__ mem, float* __restrict__ out)
{
    extern __shared__ __align__(16) char sm[];
    __half* Aw = (__half*)sm;                  // [buf][64][72]
    __half* Bt = (__half*)(sm + 18432);        // [buf][64][72]
    float*  red = (float*)sm;                  // epilogue reuse (8KB)
    const uint32_t sbA = smem_u32(Aw), sbB = smem_u32(Bt);
    const int tid = threadIdx.x, w = tid >> 5, t = tid & 31;
    const int d0 = blockIdx.x * 64;
    const int mi = w >> 2, nj = w & 3;
    const int wr = tid >> 3, ch = tid & 7;

    uint4 rAh, rAl; float4 rB[4];
    {
        rAh = *(const uint4*)&g_whi[wr * NPAD + ch * 8];
        rAl = *(const uint4*)&g_wlo[wr * NPAD + ch * 8];
        #pragma unroll
        for (int p = 0; p < 4; p++) {
            const int idx = tid + 256 * p, row = idx >> 4, c4 = idx & 15;
            const int n = row < N ? row : 0;
            rB[p] = *(const float4*)&mem[(long long)n * D + d0 + c4 * 4];
        }
    }

    float acc[2][2][4];
    #pragma unroll
    for (int af = 0; af < 2; af++)
        #pragma unroll
        for (int bf = 0; bf < 2; bf++)
            #pragma unroll
            for (int i = 0; i < 4; i++) acc[af][bf][i] = 0.f;

    for (int it = 0; it < RIT; ++it) {
        const int buf = it & 1;
        __half* A  = Aw + buf * 64 * 72;
        __half* Bm = Bt + buf * 64 * 72;
        *(uint4*)&A[wr * 72 + ch * 8]        = rAh;
        *(uint4*)&A[(32 + wr) * 72 + ch * 8] = rAl;
        #pragma unroll
        for (int p = 0; p < 4; p++) {
            const int idx = tid + 256 * p, row = idx >> 4, c4 = idx & 15;
            *(uint2*)&Bm[row * 72 + c4 * 4] = make_uint2(h2(rB[p].x, rB[p].y), h2(rB[p].z, rB[p].w));
        }
        __syncthreads();
        if (it + 1 < RIT) {
            const int nb = (it + 1) * 64;
            rAh = *(const uint4*)&g_whi[wr * NPAD + nb + ch * 8];
            rAl = *(const uint4*)&g_wlo[wr * NPAD + nb + ch * 8];
            #pragma unroll
            for (int p = 0; p < 4; p++) {
                const int idx = tid + 256 * p, row = idx >> 4, c4 = idx & 15;
                const int n = nb + row;
                const int nn = n < N ? n : 0;
                rB[p] = *(const float4*)&mem[(long long)nn * D + d0 + c4 * 4];
            }
        }
        const int lr = (t & 7) + 8 * ((t >> 3) & 1);
        const int lh = 8 * (t >> 4);
        #pragma unroll
        for (int kk = 0; kk < 4; kk++) {
            uint32_t a[2][4], bq[4];
            #pragma unroll
            for (int af = 0; af < 2; af++) {
                const uint32_t addr = sbA + 2u * (buf * 64 * 72 + (mi * 32 + af * 16 + lr) * 72 + kk * 16 + lh);
                ldm4(a[af][0], a[af][1], a[af][2], a[af][3], addr);
            }
            {
                const uint32_t addr = sbB + 2u * (buf * 64 * 72 + (kk * 16 + lr) * 72 + nj * 16 + lh);
                ldm4t(bq[0], bq[1], bq[2], bq[3], addr);
            }
            #pragma unroll
            for (int af = 0; af < 2; af++) {
                mma_h(acc[af][0], a[af][0], a[af][1], a[af][2], a[af][3], bq[0], bq[1]);
                mma_h(acc[af][1], a[af][0], a[af][1], a[af][2], a[af][3], bq[2], bq[3]);
            }
        }
        __syncthreads();
    }

    // epilogue: mi=1 (w_lo product) added into mi=0 (w_hi product)
    if (mi == 1) {
        #pragma unroll
        for (int af = 0; af < 2; af++)
            #pragma unroll
            for (int bf = 0; bf < 2; bf++)
                #pragma unroll
                for (int i = 0; i < 4; i++)
                    red[(nj * 32 + t) * 16 + af * 8 + bf * 4 + i] = acc[af][bf][i];
    }
    __syncthreads();
    if (mi == 0) {
        #pragma unroll
        for (int af = 0; af < 2; af++)
            #pragma unroll
            for (int bf = 0; bf < 2; bf++) {
                const float c0 = acc[af][bf][0] + red[(nj * 32 + t) * 16 + af * 8 + bf * 4 + 0];
                const float c1 = acc[af][bf][1] + red[(nj * 32 + t) * 16 + af * 8 + bf * 4 + 1];
                const float c2 = acc[af][bf][2] + red[(nj * 32 + t) * 16 + af * 8 + bf * 4 + 2];
                const float c3 = acc[af][bf][3] + red[(nj * 32 + t) * 16 + af * 8 + bf * 4 + 3];
                const int b   = af * 16 + (t >> 2);
                const int col = d0 + nj * 16 + bf * 8 + 2 * (t & 3);
                *(float2*)&out[b * D + col]       = make_float2(c0, c1);
                *(float2*)&out[(b + 8) * D + col] = make_float2(c2, c3);
            }
    }
}

// ---------------------------------------------------------------------------
extern "C" void kernel_launch(void* const* d_in, const int* in_sizes, int n_in,
                              void* d_out, int out_size)
{
    const float* key = (const float*)d_in[0];
    const float* mem = (const float*)d_in[1];
    float* out = (float*)d_out;

    cudaFuncSetAttribute(read_kernel, cudaFuncAttributeMaxDynamicSharedMemorySize, 36864);

    prepack_kernel<<<ITOT * 4 * 32 / 256, 256>>>(key);
    dots_kernel<<<dim3(16, KC), 256>>>(mem);
    softmax_kernel<<<32, 256>>>(key);
    read_kernel<<<D / 64, 256, 36864>>>(mem, out);
}